// round 9
// baseline (speedup 1.0000x reference)
#include <cuda_runtime.h>
#include <math.h>
#include <stdint.h>

#define BB 32
#define NN 1024
#define CC 512
#define DD 768
#define EPS 1e-6f

// ---------------- scratch ----------------------------------------------------
__device__ float d_tn[CC * DD];                  // normalized t
__device__ float d_gn[BB * DD];                  // normalized g
__device__ float d_rnp[BB * NN];                 // 1/max(||p_row||,eps)
__device__ float d_h32[NN * DD];                 // tf32-rounded h
__device__ float d_m[(size_t)BB * NN * CC];      // logits -> probs (64MB)

// ---------------- helpers ----------------------------------------------------
__device__ __forceinline__ uint32_t smem_u32(const void* p) {
    uint32_t a;
    asm("{ .reg .u64 t; cvta.to.shared.u64 t, %1; cvt.u32.u64 %0, t; }" : "=r"(a) : "l"(p));
    return a;
}
__device__ __forceinline__ float tf32r(float x) {
    uint32_t r;
    asm("cvt.rna.tf32.f32 %0, %1;" : "=r"(r) : "f"(x));
    return __uint_as_float(r);
}
__device__ __forceinline__ void cp16(uint32_t dst, const void* src) {
    asm volatile("cp.async.cg.shared.global [%0], [%1], 16;" :: "r"(dst), "l"(src));
}
#define CP_COMMIT() asm volatile("cp.async.commit_group;" ::: "memory")
#define CP_WAIT1()  asm volatile("cp.async.wait_group 1;" ::: "memory")
#define CP_WAIT0()  asm volatile("cp.async.wait_group 0;" ::: "memory")

__device__ __forceinline__ void mma_tf32(float* c, const uint32_t* a, const uint32_t* b) {
    asm volatile(
        "mma.sync.aligned.m16n8k8.row.col.f32.tf32.tf32.f32 "
        "{%0,%1,%2,%3}, {%4,%5,%6,%7}, {%8,%9}, {%0,%1,%2,%3};"
        : "+f"(c[0]), "+f"(c[1]), "+f"(c[2]), "+f"(c[3])
        : "r"(a[0]), "r"(a[1]), "r"(a[2]), "r"(a[3]), "r"(b[0]), "r"(b[1]));
}

__device__ __forceinline__ float block_reduce_sum(float v) {
    __shared__ float sh[8];
    int lane = threadIdx.x & 31, w = threadIdx.x >> 5;
#pragma unroll
    for (int o = 16; o; o >>= 1) v += __shfl_xor_sync(0xffffffffu, v, o);
    if (!lane) sh[w] = v;
    __syncthreads();
    if (w == 0) {
        float x = (lane < ((int)blockDim.x + 31) / 32) ? sh[lane] : 0.f;
#pragma unroll
        for (int o = 4; o; o >>= 1) x += __shfl_xor_sync(0xffffffffu, x, o);
        if (!lane) sh[0] = x;
    }
    __syncthreads();
    float r = sh[0];
    __syncthreads();
    return r;
}

// ---------------- prologue ---------------------------------------------------
__global__ void norm_t_kernel(const float* __restrict__ t) {
    int row = blockIdx.x;
    int i = threadIdx.x * 4;
    float4 v = *(const float4*)(t + (size_t)row * DD + i);
    float ss = block_reduce_sum(v.x * v.x + v.y * v.y + v.z * v.z + v.w * v.w);
    float s = 1.f / fmaxf(sqrtf(ss), EPS);
    *(float4*)(d_tn + (size_t)row * DD + i) = make_float4(v.x * s, v.y * s, v.z * s, v.w * s);
}

__global__ void norm_g_kernel(const float* __restrict__ g) {
    int row = blockIdx.x;
    int i = threadIdx.x * 4;
    float4 v = *(const float4*)(g + (size_t)row * DD + i);
    float ss = block_reduce_sum(v.x * v.x + v.y * v.y + v.z * v.z + v.w * v.w);
    float s = 1.f / fmaxf(sqrtf(ss), EPS);
    *(float4*)(d_gn + (size_t)row * DD + i) = make_float4(v.x * s, v.y * s, v.z * s, v.w * s);
}

__global__ void pnorm_kernel(const float* __restrict__ p) {
    int row = blockIdx.x;
    float4 v = *(const float4*)(p + (size_t)row * DD + threadIdx.x * 4);
    float ss = block_reduce_sum(v.x * v.x + v.y * v.y + v.z * v.z + v.w * v.w);
    if (threadIdx.x == 0) d_rnp[row] = 1.f / fmaxf(sqrtf(ss), EPS);
}

__global__ void h32_kernel(const float* __restrict__ h) {
    int row = blockIdx.x;
    int i = threadIdx.x * 4;
    float4 v = *(const float4*)(h + (size_t)row * DD + i);
    *(float4*)(d_h32 + (size_t)row * DD + i) =
        make_float4(tf32r(v.x), tf32r(v.y), tf32r(v.z), tf32r(v.w));
}

// ---------------- GEMM1: m[b][n][c] = rnp[n] * p[n,:].(tn[c,:]*gn[b,:]) ------
// A = raw p, B = raw tn staged via cp.async; a per-chunk in-place smem pass
// applies tf32 rounding (A) and gate*round (B). Mainloop is pure LDS+HMMA.
#define G1_STRIDE 36
#define G1_BUF (128 * G1_STRIDE)
#define G1_GOFF (4 * G1_BUF)
#define G1_SMEM ((G1_GOFF + DD) * 4)

__global__ __launch_bounds__(256, 2) void gemm1_kernel(const float* __restrict__ p) {
    extern __shared__ float sm[];
    int tid = threadIdx.x;
    int wid = tid >> 5, lane = tid & 31;
    int b = blockIdx.z;
    int nTile = blockIdx.x * 128;
    int cTile = blockIdx.y * 128;

    const float* Ag = p + ((size_t)b * NN + nTile) * DD;
    const float* Bg = d_tn + (size_t)cTile * DD;
    float* sg = sm + G1_GOFF;

    for (int i = tid; i < DD; i += 256) sg[i] = d_gn[(size_t)b * DD + i];

    uint32_t smb = smem_u32(sm);
    int srow = tid >> 3;
    int skq = (tid & 7) << 2;

    float acc[4][4][4];
#pragma unroll
    for (int mi = 0; mi < 4; mi++)
#pragma unroll
        for (int ni = 0; ni < 4; ni++)
#pragma unroll
            for (int q = 0; q < 4; q++) acc[mi][ni][q] = 0.f;

    int warpM = (wid & 1) * 64;
    int warpN = (wid >> 1) * 32;

    const int NCH = DD / 32;  // 24

    {
        uint32_t aB = smb;
        uint32_t bB = smb + G1_BUF * 4;
#pragma unroll
        for (int j = 0; j < 4; j++) {
            int r = srow + 32 * j;
            uint32_t so = (uint32_t)(r * G1_STRIDE + skq) * 4;
            cp16(aB + so, Ag + (size_t)r * DD + skq);
            cp16(bB + so, Bg + (size_t)r * DD + skq);
        }
    }
    CP_COMMIT();

    for (int i = 0; i < NCH; i++) {
        if (i + 1 < NCH) {
            int nb = (i + 1) & 1;
            int k0 = (i + 1) * 32;
            uint32_t aB = smb + (uint32_t)(nb * 2 * G1_BUF) * 4;
            uint32_t bB = aB + G1_BUF * 4;
#pragma unroll
            for (int j = 0; j < 4; j++) {
                int r = srow + 32 * j;
                uint32_t so = (uint32_t)(r * G1_STRIDE + skq) * 4;
                cp16(aB + so, Ag + (size_t)r * DD + k0 + skq);
                cp16(bB + so, Bg + (size_t)r * DD + k0 + skq);
            }
            CP_COMMIT();
            CP_WAIT1();
        } else {
            CP_WAIT0();
        }
        __syncthreads();

        float* Ab = sm + (i & 1) * 2 * G1_BUF;
        float* Bb = Ab + G1_BUF;

        // in-place transform: A -> tf32(A); B -> tf32(B * g)
        {
            float4 gv = *(const float4*)&sg[i * 32 + skq];  // same k-quad for all j
#pragma unroll
            for (int j = 0; j < 4; j++) {
                int off = (srow + 32 * j) * G1_STRIDE + skq;
                float4 a = *(float4*)&Ab[off];
                *(float4*)&Ab[off] = make_float4(tf32r(a.x), tf32r(a.y), tf32r(a.z), tf32r(a.w));
                float4 bv = *(float4*)&Bb[off];
                *(float4*)&Bb[off] = make_float4(tf32r(bv.x * gv.x), tf32r(bv.y * gv.y),
                                                 tf32r(bv.z * gv.z), tf32r(bv.w * gv.w));
            }
        }
        __syncthreads();

        const float* A = Ab;
        const float* B = Bb;
#pragma unroll
        for (int kk = 0; kk < 32; kk += 8) {
            uint32_t af[4][4], bf[4][2];
            int k = kk + (lane & 3);
#pragma unroll
            for (int mi = 0; mi < 4; mi++) {
                int r = warpM + mi * 16 + (lane >> 2);
                af[mi][0] = *(const uint32_t*)&A[r * G1_STRIDE + k];
                af[mi][1] = *(const uint32_t*)&A[(r + 8) * G1_STRIDE + k];
                af[mi][2] = *(const uint32_t*)&A[r * G1_STRIDE + k + 4];
                af[mi][3] = *(const uint32_t*)&A[(r + 8) * G1_STRIDE + k + 4];
            }
#pragma unroll
            for (int ni = 0; ni < 4; ni++) {
                int cq = warpN + ni * 8 + (lane >> 2);
                bf[ni][0] = *(const uint32_t*)&B[cq * G1_STRIDE + k];
                bf[ni][1] = *(const uint32_t*)&B[cq * G1_STRIDE + k + 4];
            }
#pragma unroll
            for (int mi = 0; mi < 4; mi++)
#pragma unroll
                for (int ni = 0; ni < 4; ni++) mma_tf32(acc[mi][ni], af[mi], bf[ni]);
        }
        __syncthreads();
    }

    // epilogue: scale rows by rnp, store logits
#pragma unroll
    for (int mi = 0; mi < 4; mi++) {
        int r0 = nTile + warpM + mi * 16 + (lane >> 2);
        int r1 = r0 + 8;
        float s0 = d_rnp[b * NN + r0];
        float s1 = d_rnp[b * NN + r1];
        float* row0 = d_m + ((size_t)b * NN + r0) * CC + cTile;
        float* row1 = d_m + ((size_t)b * NN + r1) * CC + cTile;
#pragma unroll
        for (int ni = 0; ni < 4; ni++) {
            int col = warpN + ni * 8 + (lane & 3) * 2;
            *(float2*)(row0 + col) = make_float2(acc[mi][ni][0] * s0, acc[mi][ni][1] * s0);
            *(float2*)(row1 + col) = make_float2(acc[mi][ni][2] * s1, acc[mi][ni][3] * s1);
        }
    }
}

// ---------------- softmax over n (|logit| <= 1, no max pass needed) ----------
__global__ __launch_bounds__(256) void softmax_kernel() {
    int b = blockIdx.x;
    int cx = threadIdx.x & 63;
    int part = threadIdx.x >> 6;  // 0..3
    int c = blockIdx.y * 64 + cx;
    float* base = d_m + (size_t)b * NN * CC;
    int n0 = part * 256, n1 = n0 + 256;

    __shared__ float sred[4][64];
    float s = 0.f;
    for (int n = n0; n < n1; n++) s += __expf(base[(size_t)n * CC + c]);
    sred[part][cx] = s;
    __syncthreads();
    s = (sred[0][cx] + sred[1][cx]) + (sred[2][cx] + sred[3][cx]);
    float inv = 1.f / s;
    for (int n = n0; n < n1; n++) {
        size_t idx = (size_t)n * CC + c;
        base[idx] = tf32r(__expf(base[idx]) * inv);
    }
}

// ---------------- GEMM2: out[b][c][d] = sum_n m[b][n][c] * h32[n][d] ---------
#define G2_STRIDE 136
#define G2_BUF (32 * G2_STRIDE)
#define G2_SMEM (4 * G2_BUF * 4)

__global__ __launch_bounds__(256, 2) void gemm2_kernel(float* __restrict__ out) {
    extern __shared__ float sm[];
    int tid = threadIdx.x;
    int wid = tid >> 5, lane = tid & 31;
    int b = blockIdx.z;
    int dTile = blockIdx.x * 128;
    int cTile = blockIdx.y * 128;

    const float* Ag = d_m + (size_t)b * NN * CC + cTile;   // [k=n][c]
    const float* Bg = d_h32 + dTile;                       // [k=n][d]

    uint32_t smb = smem_u32(sm);
    int skk = tid >> 5;
    int sc4 = (tid & 31) << 2;

    float acc[4][4][4];
#pragma unroll
    for (int mi = 0; mi < 4; mi++)
#pragma unroll
        for (int ni = 0; ni < 4; ni++)
#pragma unroll
            for (int q = 0; q < 4; q++) acc[mi][ni][q] = 0.f;

    int warpM = (wid & 1) * 64;   // c
    int warpN = (wid >> 1) * 32;  // d

    const int NCH = NN / 32;  // 32

    {
        uint32_t aB = smb;
        uint32_t bB = smb + G2_BUF * 4;
#pragma unroll
        for (int j = 0; j < 4; j++) {
            int kk = skk + 8 * j;
            uint32_t so = (uint32_t)(kk * G2_STRIDE + sc4) * 4;
            cp16(aB + so, Ag + (size_t)kk * CC + sc4);
            cp16(bB + so, Bg + (size_t)kk * DD + sc4);
        }
    }
    CP_COMMIT();

    for (int i = 0; i < NCH; i++) {
        if (i + 1 < NCH) {
            int nb = (i + 1) & 1;
            int k0 = (i + 1) * 32;
            uint32_t aB = smb + (uint32_t)(nb * 2 * G2_BUF) * 4;
            uint32_t bB = aB + G2_BUF * 4;
#pragma unroll
            for (int j = 0; j < 4; j++) {
                int kk = skk + 8 * j;
                uint32_t so = (uint32_t)(kk * G2_STRIDE + sc4) * 4;
                cp16(aB + so, Ag + (size_t)(k0 + kk) * CC + sc4);
                cp16(bB + so, Bg + (size_t)(k0 + kk) * DD + sc4);
            }
            CP_COMMIT();
            CP_WAIT1();
        } else {
            CP_WAIT0();
        }
        __syncthreads();

        const float* A = sm + (i & 1) * 2 * G2_BUF;
        const float* B = A + G2_BUF;
#pragma unroll
        for (int kk = 0; kk < 32; kk += 8) {
            uint32_t af[4][4], bf[4][2];
#pragma unroll
            for (int mi = 0; mi < 4; mi++) {
                int r = warpM + mi * 16 + (lane >> 2);
                int k = kk + (lane & 3);
                af[mi][0] = *(const uint32_t*)&A[k * G2_STRIDE + r];
                af[mi][1] = *(const uint32_t*)&A[k * G2_STRIDE + r + 8];
                af[mi][2] = *(const uint32_t*)&A[(k + 4) * G2_STRIDE + r];
                af[mi][3] = *(const uint32_t*)&A[(k + 4) * G2_STRIDE + r + 8];
            }
#pragma unroll
            for (int ni = 0; ni < 4; ni++) {
                int cq = warpN + ni * 8 + (lane >> 2);
                int k = kk + (lane & 3);
                bf[ni][0] = *(const uint32_t*)&B[k * G2_STRIDE + cq];
                bf[ni][1] = *(const uint32_t*)&B[(k + 4) * G2_STRIDE + cq];
            }
#pragma unroll
            for (int mi = 0; mi < 4; mi++)
#pragma unroll
                for (int ni = 0; ni < 4; ni++) mma_tf32(acc[mi][ni], af[mi], bf[ni]);
        }
        __syncthreads();
    }

#pragma unroll
    for (int mi = 0; mi < 4; mi++) {
        int c0 = cTile + warpM + mi * 16 + (lane >> 2);
        float* row0 = out + ((size_t)b * CC + c0) * DD + dTile;
        float* row1 = out + ((size_t)b * CC + c0 + 8) * DD + dTile;
#pragma unroll
        for (int ni = 0; ni < 4; ni++) {
            int col = warpN + ni * 8 + (lane & 3) * 2;
            *(float2*)(row0 + col) = make_float2(acc[mi][ni][0], acc[mi][ni][1]);
            *(float2*)(row1 + col) = make_float2(acc[mi][ni][2], acc[mi][ni][3]);
        }
    }
}

// ---------------- launch -----------------------------------------------------
extern "C" void kernel_launch(void* const* d_in, const int* in_sizes, int n_in,
                              void* d_out, int out_size) {
    const float* p = (const float*)d_in[0];
    const float* t = (const float*)d_in[1];
    const float* g = (const float*)d_in[2];
    const float* h = (const float*)d_in[3];
    float* out = (float*)d_out;

    cudaFuncSetAttribute(gemm1_kernel, cudaFuncAttributeMaxDynamicSharedMemorySize, G1_SMEM);
    cudaFuncSetAttribute(gemm2_kernel, cudaFuncAttributeMaxDynamicSharedMemorySize, G2_SMEM);

    norm_t_kernel<<<CC, 192>>>(t);
    norm_g_kernel<<<BB, 192>>>(g);
    pnorm_kernel<<<BB * NN, 192>>>(p);
    h32_kernel<<<NN, 192>>>(h);

    gemm1_kernel<<<dim3(NN / 128, CC / 128, BB), 256, G1_SMEM>>>(p);
    softmax_kernel<<<dim3(BB, CC / 64), 256>>>();
    gemm2_kernel<<<dim3(DD / 128, CC / 128, BB), 256, G2_SMEM>>>(out);
}

// round 11
// speedup vs baseline: 1.0030x; 1.0030x over previous
#include <cuda_runtime.h>
#include <math.h>
#include <stdint.h>

#define BB 32
#define NN 1024
#define CC 512
#define DD 768
#define EPS 1e-6f

// ---------------- scratch ----------------------------------------------------
__device__ float d_tn[CC * DD];                  // normalized t
__device__ float d_gn[BB * DD];                  // normalized g
__device__ float d_rnp[BB * NN];                 // 1/max(||p_row||,eps)
__device__ float d_h32[NN * DD];                 // tf32-rounded h
__device__ float d_m[(size_t)BB * NN * CC];      // logits -> probs (64MB)

// ---------------- helpers ----------------------------------------------------
__device__ __forceinline__ uint32_t smem_u32(const void* p) {
    uint32_t a;
    asm("{ .reg .u64 t; cvta.to.shared.u64 t, %1; cvt.u32.u64 %0, t; }" : "=r"(a) : "l"(p));
    return a;
}
__device__ __forceinline__ float tf32r(float x) {
    uint32_t r;
    asm("cvt.rna.tf32.f32 %0, %1;" : "=r"(r) : "f"(x));
    return __uint_as_float(r);
}
__device__ __forceinline__ void cp16(uint32_t dst, const void* src) {
    asm volatile("cp.async.cg.shared.global [%0], [%1], 16;" :: "r"(dst), "l"(src));
}
#define CP_COMMIT() asm volatile("cp.async.commit_group;" ::: "memory")
#define CP_WAIT1()  asm volatile("cp.async.wait_group 1;" ::: "memory")
#define CP_WAIT0()  asm volatile("cp.async.wait_group 0;" ::: "memory")

__device__ __forceinline__ void mma_tf32(float* c, const uint32_t* a, const uint32_t* b) {
    asm volatile(
        "mma.sync.aligned.m16n8k8.row.col.f32.tf32.tf32.f32 "
        "{%0,%1,%2,%3}, {%4,%5,%6,%7}, {%8,%9}, {%0,%1,%2,%3};"
        : "+f"(c[0]), "+f"(c[1]), "+f"(c[2]), "+f"(c[3])
        : "r"(a[0]), "r"(a[1]), "r"(a[2]), "r"(a[3]), "r"(b[0]), "r"(b[1]));
}

__device__ __forceinline__ float block_reduce_sum(float v) {
    __shared__ float sh[8];
    int lane = threadIdx.x & 31, w = threadIdx.x >> 5;
#pragma unroll
    for (int o = 16; o; o >>= 1) v += __shfl_xor_sync(0xffffffffu, v, o);
    if (!lane) sh[w] = v;
    __syncthreads();
    if (w == 0) {
        float x = (lane < ((int)blockDim.x + 31) / 32) ? sh[lane] : 0.f;
#pragma unroll
        for (int o = 4; o; o >>= 1) x += __shfl_xor_sync(0xffffffffu, x, o);
        if (!lane) sh[0] = x;
    }
    __syncthreads();
    float r = sh[0];
    __syncthreads();
    return r;
}

// ---------------- prologue ---------------------------------------------------
__global__ void norm_t_kernel(const float* __restrict__ t) {
    int row = blockIdx.x;
    int i = threadIdx.x * 4;
    float4 v = *(const float4*)(t + (size_t)row * DD + i);
    float ss = block_reduce_sum(v.x * v.x + v.y * v.y + v.z * v.z + v.w * v.w);
    float s = 1.f / fmaxf(sqrtf(ss), EPS);
    *(float4*)(d_tn + (size_t)row * DD + i) = make_float4(v.x * s, v.y * s, v.z * s, v.w * s);
}

__global__ void norm_g_kernel(const float* __restrict__ g) {
    int row = blockIdx.x;
    int i = threadIdx.x * 4;
    float4 v = *(const float4*)(g + (size_t)row * DD + i);
    float ss = block_reduce_sum(v.x * v.x + v.y * v.y + v.z * v.z + v.w * v.w);
    float s = 1.f / fmaxf(sqrtf(ss), EPS);
    *(float4*)(d_gn + (size_t)row * DD + i) = make_float4(v.x * s, v.y * s, v.z * s, v.w * s);
}

__global__ void pnorm_kernel(const float* __restrict__ p) {
    int row = blockIdx.x;
    float4 v = *(const float4*)(p + (size_t)row * DD + threadIdx.x * 4);
    float ss = block_reduce_sum(v.x * v.x + v.y * v.y + v.z * v.z + v.w * v.w);
    if (threadIdx.x == 0) d_rnp[row] = 1.f / fmaxf(sqrtf(ss), EPS);
}

__global__ void h32_kernel(const float* __restrict__ h) {
    int row = blockIdx.x;
    int i = threadIdx.x * 4;
    float4 v = *(const float4*)(h + (size_t)row * DD + i);
    *(float4*)(d_h32 + (size_t)row * DD + i) =
        make_float4(tf32r(v.x), tf32r(v.y), tf32r(v.z), tf32r(v.w));
}

// ---------------- GEMM1: m[b][n][c] = rnp[n] * p[n,:].(tn[c,:]*gn[b,:]) ------
// A = raw p, B = raw tn staged via cp.async; a per-chunk in-place smem pass
// applies tf32 rounding (A) and gate*round (B). Mainloop is pure LDS+HMMA.
#define G1_STRIDE 36
#define G1_BUF (128 * G1_STRIDE)
#define G1_GOFF (4 * G1_BUF)
#define G1_SMEM ((G1_GOFF + DD) * 4)

__global__ __launch_bounds__(256, 2) void gemm1_kernel(const float* __restrict__ p) {
    extern __shared__ float sm[];
    int tid = threadIdx.x;
    int wid = tid >> 5, lane = tid & 31;
    int b = blockIdx.z;
    int nTile = blockIdx.x * 128;
    int cTile = blockIdx.y * 128;

    const float* Ag = p + ((size_t)b * NN + nTile) * DD;
    const float* Bg = d_tn + (size_t)cTile * DD;
    float* sg = sm + G1_GOFF;

    for (int i = tid; i < DD; i += 256) sg[i] = d_gn[(size_t)b * DD + i];

    uint32_t smb = smem_u32(sm);
    int srow = tid >> 3;
    int skq = (tid & 7) << 2;

    float acc[4][4][4];
#pragma unroll
    for (int mi = 0; mi < 4; mi++)
#pragma unroll
        for (int ni = 0; ni < 4; ni++)
#pragma unroll
            for (int q = 0; q < 4; q++) acc[mi][ni][q] = 0.f;

    int warpM = (wid & 1) * 64;
    int warpN = (wid >> 1) * 32;

    const int NCH = DD / 32;  // 24

    {
        uint32_t aB = smb;
        uint32_t bB = smb + G1_BUF * 4;
#pragma unroll
        for (int j = 0; j < 4; j++) {
            int r = srow + 32 * j;
            uint32_t so = (uint32_t)(r * G1_STRIDE + skq) * 4;
            cp16(aB + so, Ag + (size_t)r * DD + skq);
            cp16(bB + so, Bg + (size_t)r * DD + skq);
        }
    }
    CP_COMMIT();

    for (int i = 0; i < NCH; i++) {
        if (i + 1 < NCH) {
            int nb = (i + 1) & 1;
            int k0 = (i + 1) * 32;
            uint32_t aB = smb + (uint32_t)(nb * 2 * G1_BUF) * 4;
            uint32_t bB = aB + G1_BUF * 4;
#pragma unroll
            for (int j = 0; j < 4; j++) {
                int r = srow + 32 * j;
                uint32_t so = (uint32_t)(r * G1_STRIDE + skq) * 4;
                cp16(aB + so, Ag + (size_t)r * DD + k0 + skq);
                cp16(bB + so, Bg + (size_t)r * DD + k0 + skq);
            }
            CP_COMMIT();
            CP_WAIT1();
        } else {
            CP_WAIT0();
        }
        __syncthreads();

        float* Ab = sm + (i & 1) * 2 * G1_BUF;
        float* Bb = Ab + G1_BUF;

        // in-place transform: A -> tf32(A); B -> tf32(B * g)
        {
            float4 gv = *(const float4*)&sg[i * 32 + skq];  // same k-quad for all j
#pragma unroll
            for (int j = 0; j < 4; j++) {
                int off = (srow + 32 * j) * G1_STRIDE + skq;
                float4 a = *(float4*)&Ab[off];
                *(float4*)&Ab[off] = make_float4(tf32r(a.x), tf32r(a.y), tf32r(a.z), tf32r(a.w));
                float4 bv = *(float4*)&Bb[off];
                *(float4*)&Bb[off] = make_float4(tf32r(bv.x * gv.x), tf32r(bv.y * gv.y),
                                                 tf32r(bv.z * gv.z), tf32r(bv.w * gv.w));
            }
        }
        __syncthreads();

        const float* A = Ab;
        const float* B = Bb;
#pragma unroll
        for (int kk = 0; kk < 32; kk += 8) {
            uint32_t af[4][4], bf[4][2];
            int k = kk + (lane & 3);
#pragma unroll
            for (int mi = 0; mi < 4; mi++) {
                int r = warpM + mi * 16 + (lane >> 2);
                af[mi][0] = *(const uint32_t*)&A[r * G1_STRIDE + k];
                af[mi][1] = *(const uint32_t*)&A[(r + 8) * G1_STRIDE + k];
                af[mi][2] = *(const uint32_t*)&A[r * G1_STRIDE + k + 4];
                af[mi][3] = *(const uint32_t*)&A[(r + 8) * G1_STRIDE + k + 4];
            }
#pragma unroll
            for (int ni = 0; ni < 4; ni++) {
                int cq = warpN + ni * 8 + (lane >> 2);
                bf[ni][0] = *(const uint32_t*)&B[cq * G1_STRIDE + k];
                bf[ni][1] = *(const uint32_t*)&B[cq * G1_STRIDE + k + 4];
            }
#pragma unroll
            for (int mi = 0; mi < 4; mi++)
#pragma unroll
                for (int ni = 0; ni < 4; ni++) mma_tf32(acc[mi][ni], af[mi], bf[ni]);
        }
        __syncthreads();
    }

    // epilogue: scale rows by rnp, store logits
#pragma unroll
    for (int mi = 0; mi < 4; mi++) {
        int r0 = nTile + warpM + mi * 16 + (lane >> 2);
        int r1 = r0 + 8;
        float s0 = d_rnp[b * NN + r0];
        float s1 = d_rnp[b * NN + r1];
        float* row0 = d_m + ((size_t)b * NN + r0) * CC + cTile;
        float* row1 = d_m + ((size_t)b * NN + r1) * CC + cTile;
#pragma unroll
        for (int ni = 0; ni < 4; ni++) {
            int col = warpN + ni * 8 + (lane & 3) * 2;
            *(float2*)(row0 + col) = make_float2(acc[mi][ni][0] * s0, acc[mi][ni][1] * s0);
            *(float2*)(row1 + col) = make_float2(acc[mi][ni][2] * s1, acc[mi][ni][3] * s1);
        }
    }
}

// ---------------- softmax over n (|logit| <= 1, no max pass needed) ----------
__global__ __launch_bounds__(256) void softmax_kernel() {
    int b = blockIdx.x;
    int cx = threadIdx.x & 63;
    int part = threadIdx.x >> 6;  // 0..3
    int c = blockIdx.y * 64 + cx;
    float* base = d_m + (size_t)b * NN * CC;
    int n0 = part * 256, n1 = n0 + 256;

    __shared__ float sred[4][64];
    float s = 0.f;
    for (int n = n0; n < n1; n++) s += __expf(base[(size_t)n * CC + c]);
    sred[part][cx] = s;
    __syncthreads();
    s = (sred[0][cx] + sred[1][cx]) + (sred[2][cx] + sred[3][cx]);
    float inv = 1.f / s;
    for (int n = n0; n < n1; n++) {
        size_t idx = (size_t)n * CC + c;
        base[idx] = tf32r(__expf(base[idx]) * inv);
    }
}

// ---------------- GEMM2: out[b][c][d] = sum_n m[b][n][c] * h32[n][d] ---------
#define G2_STRIDE 136
#define G2_BUF (32 * G2_STRIDE)
#define G2_SMEM (4 * G2_BUF * 4)

__global__ __launch_bounds__(256, 2) void gemm2_kernel(float* __restrict__ out) {
    extern __shared__ float sm[];
    int tid = threadIdx.x;
    int wid = tid >> 5, lane = tid & 31;
    int b = blockIdx.z;
    int dTile = blockIdx.x * 128;
    int cTile = blockIdx.y * 128;

    const float* Ag = d_m + (size_t)b * NN * CC + cTile;   // [k=n][c]
    const float* Bg = d_h32 + dTile;                       // [k=n][d]

    uint32_t smb = smem_u32(sm);
    int skk = tid >> 5;
    int sc4 = (tid & 31) << 2;

    float acc[4][4][4];
#pragma unroll
    for (int mi = 0; mi < 4; mi++)
#pragma unroll
        for (int ni = 0; ni < 4; ni++)
#pragma unroll
            for (int q = 0; q < 4; q++) acc[mi][ni][q] = 0.f;

    int warpM = (wid & 1) * 64;   // c
    int warpN = (wid >> 1) * 32;  // d

    const int NCH = NN / 32;  // 32

    {
        uint32_t aB = smb;
        uint32_t bB = smb + G2_BUF * 4;
#pragma unroll
        for (int j = 0; j < 4; j++) {
            int kk = skk + 8 * j;
            uint32_t so = (uint32_t)(kk * G2_STRIDE + sc4) * 4;
            cp16(aB + so, Ag + (size_t)kk * CC + sc4);
            cp16(bB + so, Bg + (size_t)kk * DD + sc4);
        }
    }
    CP_COMMIT();

    for (int i = 0; i < NCH; i++) {
        if (i + 1 < NCH) {
            int nb = (i + 1) & 1;
            int k0 = (i + 1) * 32;
            uint32_t aB = smb + (uint32_t)(nb * 2 * G2_BUF) * 4;
            uint32_t bB = aB + G2_BUF * 4;
#pragma unroll
            for (int j = 0; j < 4; j++) {
                int kk = skk + 8 * j;
                uint32_t so = (uint32_t)(kk * G2_STRIDE + sc4) * 4;
                cp16(aB + so, Ag + (size_t)(k0 + kk) * CC + sc4);
                cp16(bB + so, Bg + (size_t)(k0 + kk) * DD + sc4);
            }
            CP_COMMIT();
            CP_WAIT1();
        } else {
            CP_WAIT0();
        }
        __syncthreads();

        const float* A = sm + (i & 1) * 2 * G2_BUF;
        const float* B = A + G2_BUF;
#pragma unroll
        for (int kk = 0; kk < 32; kk += 8) {
            uint32_t af[4][4], bf[4][2];
#pragma unroll
            for (int mi = 0; mi < 4; mi++) {
                int r = warpM + mi * 16 + (lane >> 2);
                int k = kk + (lane & 3);
                af[mi][0] = *(const uint32_t*)&A[k * G2_STRIDE + r];
                af[mi][1] = *(const uint32_t*)&A[k * G2_STRIDE + r + 8];
                af[mi][2] = *(const uint32_t*)&A[(k + 4) * G2_STRIDE + r];
                af[mi][3] = *(const uint32_t*)&A[(k + 4) * G2_STRIDE + r + 8];
            }
#pragma unroll
            for (int ni = 0; ni < 4; ni++) {
                int cq = warpN + ni * 8 + (lane >> 2);
                int k = kk + (lane & 3);
                bf[ni][0] = *(const uint32_t*)&B[k * G2_STRIDE + cq];
                bf[ni][1] = *(const uint32_t*)&B[(k + 4) * G2_STRIDE + cq];
            }
#pragma unroll
            for (int mi = 0; mi < 4; mi++)
#pragma unroll
                for (int ni = 0; ni < 4; ni++) mma_tf32(acc[mi][ni], af[mi], bf[ni]);
        }
        __syncthreads();
    }

#pragma unroll
    for (int mi = 0; mi < 4; mi++) {
        int c0 = cTile + warpM + mi * 16 + (lane >> 2);
        float* row0 = out + ((size_t)b * CC + c0) * DD + dTile;
        float* row1 = out + ((size_t)b * CC + c0 + 8) * DD + dTile;
#pragma unroll
        for (int ni = 0; ni < 4; ni++) {
            int col = warpN + ni * 8 + (lane & 3) * 2;
            *(float2*)(row0 + col) = make_float2(acc[mi][ni][0], acc[mi][ni][1]);
            *(float2*)(row1 + col) = make_float2(acc[mi][ni][2], acc[mi][ni][3]);
        }
    }
}

// ---------------- launch -----------------------------------------------------
extern "C" void kernel_launch(void* const* d_in, const int* in_sizes, int n_in,
                              void* d_out, int out_size) {
    const float* p = (const float*)d_in[0];
    const float* t = (const float*)d_in[1];
    const float* g = (const float*)d_in[2];
    const float* h = (const float*)d_in[3];
    float* out = (float*)d_out;

    cudaFuncSetAttribute(gemm1_kernel, cudaFuncAttributeMaxDynamicSharedMemorySize, G1_SMEM);
    cudaFuncSetAttribute(gemm2_kernel, cudaFuncAttributeMaxDynamicSharedMemorySize, G2_SMEM);

    norm_t_kernel<<<CC, 192>>>(t);
    norm_g_kernel<<<BB, 192>>>(g);
    pnorm_kernel<<<BB * NN, 192>>>(p);
    h32_kernel<<<NN, 192>>>(h);

    gemm1_kernel<<<dim3(NN / 128, CC / 128, BB), 256, G1_SMEM>>>(p);
    softmax_kernel<<<dim3(BB, CC / 64), 256>>>();
    gemm2_kernel<<<dim3(DD / 128, CC / 128, BB), 256, G2_SMEM>>>(out);
}